// round 1
// baseline (speedup 1.0000x reference)
#include <cuda_runtime.h>

// ---------------------------------------------------------------------------
// RelPositionMultiHeadAttention  (B=8, T=1024, H=8, D=64, F=512, L=2*T-1=2047)
//
// Pipeline:
//   1. Q = query @ Wq^T + bq   -> g_Q [B][H][T][D]
//   2. K = key   @ Wk^T + bk   -> g_K [B][H][T][D]
//   3. V = value @ Wv^T + bv   -> g_V [B][H][T][D]
//   4. P = pos_emb @ Wpos^T    -> g_P [H][L][D]
//   5. fused attention (AC + rel-shifted BD + mask + online softmax + PV)
//      -> g_X [B][T][F]
//   6. out = g_X @ Wo^T + bo
//
// rel_shift identity: shifted_bd[a,k] = q_v[a] . P[1023 + k - a]
// ---------------------------------------------------------------------------

#define BB 8
#define TT 1024
#define HH 8
#define DD 64
#define FF 512
#define LL 2047

__device__ float g_Q[BB*HH*TT*DD];
__device__ float g_K[BB*HH*TT*DD];
__device__ float g_V[BB*HH*TT*DD];
__device__ float g_P[HH*LL*DD];
__device__ float g_X[BB*TT*FF];

// ---------------------------------------------------------------------------
// Generic NT SGEMM: C[m,n] = sum_k A[m,k] * W[n,k] + bias[n]
// K = N = 512 fixed. Tile 128x128, BK=16, 256 threads, 8x8 per thread.
// layout: 0 = plain row-major MxN, 1 = scatter to [B][H][T][D], 2 = [H][L][D]
// asel: 0 = use Ain pointer, 5 = g_X.  csel: 0=Cin, 1..4 = g_Q/g_K/g_V/g_P.
// ---------------------------------------------------------------------------
__global__ __launch_bounds__(256)
void gemm_nt_kernel(const float* __restrict__ Ain, int asel,
                    const float* __restrict__ W,
                    const float* __restrict__ bias,
                    float* __restrict__ Cin, int csel,
                    int M, int layout)
{
    const int K = 512;
    const float* A = (asel == 5) ? g_X : Ain;
    float* C = Cin;
    if      (csel == 1) C = g_Q;
    else if (csel == 2) C = g_K;
    else if (csel == 3) C = g_V;
    else if (csel == 4) C = g_P;

    __shared__ float As[16][132];
    __shared__ float Bs[16][132];

    const int tid = threadIdx.x;
    const int m0 = blockIdx.y * 128;
    const int n0 = blockIdx.x * 128;
    const int tx = tid & 15;
    const int ty = tid >> 4;

    float acc[8][8];
#pragma unroll
    for (int i = 0; i < 8; i++)
#pragma unroll
        for (int j = 0; j < 8; j++) acc[i][j] = 0.0f;

    const int lr = tid >> 1;          // 0..127: row within tile
    const int lk = (tid & 1) << 3;    // 0 or 8: k offset

    for (int k0 = 0; k0 < K; k0 += 16) {
        // stage global -> registers
        float4 a0 = make_float4(0.f,0.f,0.f,0.f), a1 = make_float4(0.f,0.f,0.f,0.f);
        const int gm = m0 + lr;
        if (gm < M) {
            const float4* ap = (const float4*)(A + gm * K + k0 + lk);
            a0 = ap[0]; a1 = ap[1];
        }
        const float4* wp = (const float4*)(W + (n0 + lr) * K + k0 + lk);
        float4 b0 = wp[0], b1 = wp[1];

        __syncthreads();   // previous compute done
        As[lk+0][lr] = a0.x; As[lk+1][lr] = a0.y; As[lk+2][lr] = a0.z; As[lk+3][lr] = a0.w;
        As[lk+4][lr] = a1.x; As[lk+5][lr] = a1.y; As[lk+6][lr] = a1.z; As[lk+7][lr] = a1.w;
        Bs[lk+0][lr] = b0.x; Bs[lk+1][lr] = b0.y; Bs[lk+2][lr] = b0.z; Bs[lk+3][lr] = b0.w;
        Bs[lk+4][lr] = b1.x; Bs[lk+5][lr] = b1.y; Bs[lk+6][lr] = b1.z; Bs[lk+7][lr] = b1.w;
        __syncthreads();

#pragma unroll
        for (int kk = 0; kk < 16; kk++) {
            float a[8], b[8];
            *(float4*)(a)     = *(const float4*)&As[kk][ty*8];
            *(float4*)(a + 4) = *(const float4*)&As[kk][ty*8 + 4];
            *(float4*)(b)     = *(const float4*)&Bs[kk][tx*8];
            *(float4*)(b + 4) = *(const float4*)&Bs[kk][tx*8 + 4];
#pragma unroll
            for (int i = 0; i < 8; i++)
#pragma unroll
                for (int j = 0; j < 8; j++)
                    acc[i][j] = fmaf(a[i], b[j], acc[i][j]);
        }
    }

    // epilogue
#pragma unroll
    for (int i = 0; i < 8; i++) {
        const int m = m0 + ty*8 + i;
        if (m >= M) continue;
#pragma unroll
        for (int j = 0; j < 8; j++) {
            const int n = n0 + tx*8 + j;
            float v = acc[i][j];
            if (bias) v += bias[n];
            if (layout == 0) {
                C[m * 512 + n] = v;
            } else if (layout == 1) {
                const int b  = m >> 10, t = m & 1023;
                const int hh = n >> 6,  dd = n & 63;
                C[((b * HH + hh) * TT + t) * DD + dd] = v;
            } else { // layout 2: P [H][L][D], m = l
                const int hh = n >> 6, dd = n & 63;
                C[(hh * LL + m) * DD + dd] = v;
            }
        }
    }
}

// ---------------------------------------------------------------------------
// Fused attention. Block = (b,h, 64-query tile). 256 threads = 16x16,
// each thread owns a 4(q) x 4(k) score tile and a 4(q) x 4(d) output tile.
// ---------------------------------------------------------------------------
#define SQ 68
#define SPB 132

__device__ __forceinline__ int mask_get(const unsigned char* mb, int mode, int idx)
{
    if (mode == 1) return ((const int*)mb)[idx] != 0;
    if (mode == 2) return ((const float*)mb)[idx] != 0.0f;
    return mb[idx] != 0;
}

__global__ __launch_bounds__(256, 2)
void attn_kernel(const unsigned char* __restrict__ maskb,
                 const float* __restrict__ Ubias,
                 const float* __restrict__ Vbias)
{
    extern __shared__ float sm[];
    float* Qt  = sm;                 // [D][SQ]   Q tile, d-major
    float* KPt = Qt  + DD * SQ;      // [D][SQ] K tile (d-major) / later P tile [k][a]
    float* Vs  = KPt + DD * SQ;      // [k][SQ]   V tile, k-major
    float* Pb  = Vs  + DD * SQ;      // [D][SPB]  P band, d-major, 127 cols
    float* uv  = Pb  + DD * SPB;     // [128]     pos_bias_u | pos_bias_v

    const int tid = threadIdx.x;
    const int tx = tid & 15;
    const int ty = tid >> 4;
    const int q0 = blockIdx.x * 64;
    const int bh = blockIdx.y;
    const int b = bh >> 3, h = bh & 7;

    // --- mask dtype sniff (deterministic, same result in every thread) ---
    int mmode;
    {
        bool i32 = true, f32 = true;
#pragma unroll
        for (int i = 0; i < 32; i++) {
            unsigned char c0 = maskb[4*i+0], c1 = maskb[4*i+1];
            unsigned char c2 = maskb[4*i+2], c3 = maskb[4*i+3];
            if (c1 | c2 | c3) i32 = false;
            if (c0 | c1) f32 = false;
            if (!((c2 == 0 && c3 == 0) || (c2 == 0x80 && c3 == 0x3F))) f32 = false;
        }
        mmode = i32 ? 1 : (f32 ? 2 : 0);
    }

    // --- load Q tile (transposed) + biases ---
    const int qbase = (bh * TT + q0) * DD;
#pragma unroll
    for (int r = 0; r < 4; r++) {
        const int idx = tid + r * 256;
        const int a = idx >> 4, dq = (idx & 15) << 2;
        float4 q4 = *(const float4*)&g_Q[qbase + a * DD + dq];
        Qt[(dq+0)*SQ + a] = q4.x;
        Qt[(dq+1)*SQ + a] = q4.y;
        Qt[(dq+2)*SQ + a] = q4.z;
        Qt[(dq+3)*SQ + a] = q4.w;
    }
    if (tid < 64)        uv[tid] = Ubias[h * DD + tid];
    else if (tid < 128)  uv[tid] = Vbias[h * DD + tid - 64];

    float mi[4], li[4], O[4][4];
#pragma unroll
    for (int i = 0; i < 4; i++) {
        mi[i] = -1e30f; li[i] = 0.0f;
#pragma unroll
        for (int j = 0; j < 4; j++) O[i][j] = 0.0f;
    }

    for (int kt = 0; kt < 16; kt++) {
        __syncthreads();   // prior PV reads of KPt/Vs done, Qt/uv visible

        // --- load K (transposed), V (direct) ---
        const int kvbase = (bh * TT + kt * 64) * DD;
#pragma unroll
        for (int r = 0; r < 4; r++) {
            const int idx = tid + r * 256;
            const int k = idx >> 4, dq = (idx & 15) << 2;
            float4 k4 = *(const float4*)&g_K[kvbase + k * DD + dq];
            KPt[(dq+0)*SQ + k] = k4.x;
            KPt[(dq+1)*SQ + k] = k4.y;
            KPt[(dq+2)*SQ + k] = k4.z;
            KPt[(dq+3)*SQ + k] = k4.w;
            float4 v4 = *(const float4*)&g_V[kvbase + k * DD + dq];
            *(float4*)&Vs[k * SQ + dq] = v4;
        }
        // --- load P band rows [lbase-63, lbase+63], transposed ---
        const int lbase = 1023 + kt * 64 - q0;
        const int pbase = (h * LL + (lbase - 63)) * DD;
#pragma unroll
        for (int r = 0; r < 8; r++) {
            const int idx = tid + r * 256;
            const int ll = idx >> 4, dq = (idx & 15) << 2;
            if (ll < 127) {
                float4 p4 = *(const float4*)&g_P[pbase + ll * DD + dq];
                Pb[(dq+0)*SPB + ll] = p4.x;
                Pb[(dq+1)*SPB + ll] = p4.y;
                Pb[(dq+2)*SPB + ll] = p4.z;
                Pb[(dq+3)*SPB + ll] = p4.w;
            }
        }
        __syncthreads();

        // --- scores: AC + BD ---
        float s[4][4];
#pragma unroll
        for (int i = 0; i < 4; i++)
#pragma unroll
            for (int j = 0; j < 4; j++) s[i][j] = 0.0f;

#pragma unroll 4
        for (int d = 0; d < DD; d++) {
            float4 q4 = *(const float4*)&Qt[d * SQ + ty * 4];
            float4 k4 = *(const float4*)&KPt[d * SQ + tx * 4];
            const float u = uv[d], v = uv[64 + d];
            const float* pbp = &Pb[d * SPB + 60 + (tx - ty) * 4];
            float pv[7];
#pragma unroll
            for (int t = 0; t < 7; t++) pv[t] = pbp[t];
            float qa[4] = {q4.x, q4.y, q4.z, q4.w};
            float kk[4] = {k4.x, k4.y, k4.z, k4.w};
#pragma unroll
            for (int i = 0; i < 4; i++) {
                const float qu = qa[i] + u;
                const float qv = qa[i] + v;
#pragma unroll
                for (int j = 0; j < 4; j++) {
                    s[i][j] = fmaf(qu, kk[j], s[i][j]);
                    s[i][j] = fmaf(qv, pv[3 + j - i], s[i][j]);
                }
            }
        }
        __syncthreads();   // done reading KPt as K

        // --- scale + mask ---
        const int kg0 = kt * 64 + tx * 4;
#pragma unroll
        for (int i = 0; i < 4; i++) {
            const int ridx = (b * TT + q0 + ty * 4 + i) * TT + kg0;
#pragma unroll
            for (int j = 0; j < 4; j++) {
                const int mk = mask_get(maskb, mmode, ridx + j);
                s[i][j] = mk ? -10000.0f : s[i][j] * 0.125f;
            }
        }

        // --- online softmax update ---
#pragma unroll
        for (int i = 0; i < 4; i++) {
            float rm = fmaxf(fmaxf(s[i][0], s[i][1]), fmaxf(s[i][2], s[i][3]));
#pragma unroll
            for (int o = 8; o >= 1; o >>= 1)
                rm = fmaxf(rm, __shfl_xor_sync(0xffffffffu, rm, o));
            const float mnew  = fmaxf(mi[i], rm);
            const float alpha = __expf(mi[i] - mnew);
            float rsum = 0.0f;
#pragma unroll
            for (int j = 0; j < 4; j++) {
                float p = (s[i][j] == -10000.0f) ? 0.0f : __expf(s[i][j] - mnew);
                s[i][j] = p;
                rsum += p;
            }
#pragma unroll
            for (int o = 8; o >= 1; o >>= 1)
                rsum += __shfl_xor_sync(0xffffffffu, rsum, o);
            li[i] = li[i] * alpha + rsum;
            mi[i] = mnew;
            O[i][0] *= alpha; O[i][1] *= alpha; O[i][2] *= alpha; O[i][3] *= alpha;
        }

        // --- store P tile transposed [k][a] into KPt ---
#pragma unroll
        for (int i = 0; i < 4; i++)
#pragma unroll
            for (int j = 0; j < 4; j++)
                KPt[(tx*4 + j) * SQ + ty*4 + i] = s[i][j];
        __syncthreads();

        // --- O += P @ V ---
#pragma unroll 8
        for (int k = 0; k < 64; k++) {
            float4 p4 = *(const float4*)&KPt[k * SQ + ty * 4];
            float4 v4 = *(const float4*)&Vs[k * SQ + tx * 4];
            float pa[4] = {p4.x, p4.y, p4.z, p4.w};
            float va[4] = {v4.x, v4.y, v4.z, v4.w};
#pragma unroll
            for (int i = 0; i < 4; i++)
#pragma unroll
                for (int j = 0; j < 4; j++)
                    O[i][j] = fmaf(pa[i], va[j], O[i][j]);
        }
    }

    // --- epilogue: normalize, write X[b][t][h*64+d] ---
#pragma unroll
    for (int i = 0; i < 4; i++) {
        const float invl = (li[i] > 0.0f) ? (1.0f / li[i]) : 0.0f;
        float4 o4 = make_float4(O[i][0]*invl, O[i][1]*invl, O[i][2]*invl, O[i][3]*invl);
        *(float4*)&g_X[(b * TT + q0 + ty*4 + i) * FF + h * DD + tx * 4] = o4;
    }
}

// ---------------------------------------------------------------------------
// launcher
// ---------------------------------------------------------------------------
extern "C" void kernel_launch(void* const* d_in, const int* in_sizes, int n_in,
                              void* d_out, int out_size)
{
    const float* query   = (const float*)d_in[0];
    const float* key     = (const float*)d_in[1];
    const float* value   = (const float*)d_in[2];
    const unsigned char* mask = (const unsigned char*)d_in[3];
    const float* pos_emb = (const float*)d_in[4];
    const float* Wq  = (const float*)d_in[5];
    const float* bq  = (const float*)d_in[6];
    const float* Wk  = (const float*)d_in[7];
    const float* bk  = (const float*)d_in[8];
    const float* Wv  = (const float*)d_in[9];
    const float* bv  = (const float*)d_in[10];
    const float* Wpos= (const float*)d_in[11];
    const float* Wo  = (const float*)d_in[12];
    const float* bo  = (const float*)d_in[13];
    const float* pbu = (const float*)d_in[14];
    const float* pbv = (const float*)d_in[15];
    float* out = (float*)d_out;

    const dim3 gq(4, 64);   // N/128, 8192/128
    const dim3 gp(4, 16);   // N/128, ceil(2047/128)

    gemm_nt_kernel<<<gq, 256>>>(query,   0, Wq,   bq,      nullptr, 1, BB*TT, 1);
    gemm_nt_kernel<<<gq, 256>>>(key,     0, Wk,   bk,      nullptr, 2, BB*TT, 1);
    gemm_nt_kernel<<<gq, 256>>>(value,   0, Wv,   bv,      nullptr, 3, BB*TT, 1);
    gemm_nt_kernel<<<gp, 256>>>(pos_emb, 0, Wpos, nullptr, nullptr, 4, LL,    2);

    const size_t smem = (size_t)(DD*SQ*3 + DD*SPB + 128) * sizeof(float);
    cudaFuncSetAttribute((const void*)attn_kernel,
                         cudaFuncAttributeMaxDynamicSharedMemorySize, (int)smem);
    attn_kernel<<<dim3(16, 64), 256, smem>>>(mask, pbu, pbv);

    gemm_nt_kernel<<<gq, 256>>>(nullptr, 5, Wo, bo, out, 0, BB*TT, 0);
}